// round 3
// baseline (speedup 1.0000x reference)
#include <cuda_runtime.h>
#include <math.h>

constexpr int Bc = 4, Sc = 512, Dc = 512, Ic = 1024, Cc = 32, NCc = 16;

// ---------------- persistent device scratch ----------------
__device__ float g_k[Bc*Sc*Dc];
__device__ float g_v[Bc*Sc*Dc];
__device__ float g_q[Bc*Sc*Dc];
__device__ float g_theta[Bc*Sc];
__device__ float g_alpha[Bc*Sc];
__device__ float g_eta[Bc*Sc];
__device__ float g_MW1[Bc*Ic*Dc];
__device__ float g_SW1[Bc*Ic*Dc];
__device__ float g_MW2[Bc*Dc*Ic];
__device__ float g_SW2[Bc*Dc*Ic];
__device__ float g_Mln[Bc*Dc];
__device__ float g_Sln[Bc*Dc];
__device__ float g_z[Bc*Cc*Ic];
__device__ float g_h[Bc*Cc*Ic];
__device__ float g_o[Bc*Cc*Dc];
__device__ float g_do[Bc*Cc*Dc];
__device__ float g_gln[Bc*Cc*Dc];
__device__ float g_p[Bc*Cc*Ic];
__device__ float g_nk[Bc*Cc], g_ndo[Bc*Cc], g_ngl[Bc*Cc], g_np[Bc*Cc], g_nh[Bc*Cc];
__device__ float g_ce[Bc*Cc], g_ccoef[Bc*Cc];
__device__ float g_A[Bc], g_Bp[Bc], g_cS[Bc];
__device__ float g_hbuf[Bc*Sc*Ic];
__device__ float g_obuf[Bc*Sc*Dc];

__device__ __forceinline__ float sigmoidf(float x){ return 1.f/(1.f+expf(-x)); }

__device__ __forceinline__ float blockReduce(float v){
    __shared__ float sred[33];
    int lane = threadIdx.x & 31, w = threadIdx.x >> 5;
    #pragma unroll
    for(int o=16;o>0;o>>=1) v += __shfl_down_sync(0xffffffffu, v, o);
    if(lane==0) sred[w] = v;
    __syncthreads();
    int nw = (blockDim.x + 31) >> 5;
    if(w==0){
        float r = (lane < nw) ? sred[lane] : 0.f;
        #pragma unroll
        for(int o=16;o>0;o>>=1) r += __shfl_down_sync(0xffffffffu, r, o);
        if(lane==0) sred[32] = r;
    }
    __syncthreads();
    float r = sred[32];
    __syncthreads();
    return r;
}

// ---------------- init (runs every launch; deterministic) ----------------
__global__ void init_kernel(const float* __restrict__ w1, const float* __restrict__ w2,
                            const float* __restrict__ lnw){
    int idx = blockIdx.x*256 + threadIdx.x;   // covers Ic*Dc = 524288
    float a = w1[idx], b2 = w2[idx];
    #pragma unroll
    for(int b=0;b<Bc;b++){
        g_MW1[b*Ic*Dc + idx] = a;   g_SW1[b*Ic*Dc + idx] = 0.f;
        g_MW2[b*Dc*Ic + idx] = b2;  g_SW2[b*Dc*Ic + idx] = 0.f;
    }
    if(idx < Dc){
        float l = lnw[idx];
        #pragma unroll
        for(int b=0;b<Bc;b++){ g_Mln[b*Dc+idx] = l; g_Sln[b*Dc+idx] = 0.f; }
    }
}

// ---------------- NT GEMM: C[M,N] = A[M,K] @ B[N,K]^T ----------------
// tile 32x64, 256 threads, each thread 2x4 outputs.
// mode 0: store; 1: silu; 2: store raw to Z, silu to C.
__global__ __launch_bounds__(256) void gemm_nt(
    const float* __restrict__ A, long long sAz,
    const float* __restrict__ B, long long sBz,
    float* __restrict__ C, long long sCz,
    float* __restrict__ Z, long long sZz,
    int M, int N, int K, int mode)
{
    int bz = blockIdx.z;
    const float* Ab = A + bz*sAz + (long long)blockIdx.y*32*K;
    const float* Bb = B + bz*sBz + (long long)blockIdx.x*64*K;
    __shared__ float As[32][33];
    __shared__ float Bs[64][33];
    int tid = threadIdx.x;
    int tr = tid >> 4;          // 0..15 -> rows tr, tr+16
    int tc = tid & 15;          // cols tc*4 .. tc*4+3
    float acc0[4] = {0.f,0.f,0.f,0.f};
    float acc1[4] = {0.f,0.f,0.f,0.f};

    for(int k0=0;k0<K;k0+=32){
        {   // A tile: 32x32, 4 elems/thread
            int m = tid >> 3, kb = (tid & 7) * 4;
            float4 va = *(const float4*)&Ab[(long long)m*K + k0 + kb];
            As[m][kb]=va.x; As[m][kb+1]=va.y; As[m][kb+2]=va.z; As[m][kb+3]=va.w;
        }
        {   // B tile: 64x32, 8 elems/thread
            int n = tid >> 2, kb = (tid & 3) * 8;
            const float* src = &Bb[(long long)n*K + k0 + kb];
            float4 v0 = *(const float4*)src;
            float4 v1 = *(const float4*)(src+4);
            Bs[n][kb]=v0.x; Bs[n][kb+1]=v0.y; Bs[n][kb+2]=v0.z; Bs[n][kb+3]=v0.w;
            Bs[n][kb+4]=v1.x; Bs[n][kb+5]=v1.y; Bs[n][kb+6]=v1.z; Bs[n][kb+7]=v1.w;
        }
        __syncthreads();
        #pragma unroll
        for(int kk=0;kk<32;kk++){
            float a0 = As[tr][kk], a1 = As[tr+16][kk];
            #pragma unroll
            for(int j=0;j<4;j++){
                float bv = Bs[tc*4+j][kk];
                acc0[j] += a0*bv;
                acc1[j] += a1*bv;
            }
        }
        __syncthreads();
    }
    int colg = blockIdx.x*64 + tc*4;
    #pragma unroll
    for(int i=0;i<2;i++){
        int m = blockIdx.y*32 + tr + i*16;
        float* accp = i ? acc1 : acc0;
        #pragma unroll
        for(int j=0;j<4;j++){
            long long idx = bz*sCz + (long long)m*N + colg + j;
            float v = accp[j];
            if(mode == 0){ C[idx] = v; }
            else if(mode == 1){ float s = sigmoidf(v); C[idx] = v*s; }
            else { // mode 2
                Z[bz*sZz + (long long)m*N + colg + j] = v;
                float s = sigmoidf(v); C[idx] = v*s;
            }
        }
    }
}

// ---------------- NN GEMM: C[M,N] = A[M,K] @ B[K,N] ----------------
// mode 3: C = acc * dsilu(Z)
__global__ __launch_bounds__(256) void gemm_nn(
    const float* __restrict__ A, long long sAz,
    const float* __restrict__ B, long long sBz,
    float* __restrict__ C, long long sCz,
    const float* __restrict__ Z, long long sZz,
    int M, int N, int K, int mode)
{
    int bz = blockIdx.z;
    const float* Ab = A + bz*sAz + (long long)blockIdx.y*32*K;
    const float* Bb = B + bz*sBz;
    int n0 = blockIdx.x*64;
    __shared__ float As[32][33];
    __shared__ float Bs2[32][72];
    int tid = threadIdx.x;
    int tr = tid >> 4;
    int tc = tid & 15;
    float acc0[4] = {0.f,0.f,0.f,0.f};
    float acc1[4] = {0.f,0.f,0.f,0.f};

    for(int k0=0;k0<K;k0+=32){
        {
            int m = tid >> 3, kb = (tid & 7) * 4;
            float4 va = *(const float4*)&Ab[(long long)m*K + k0 + kb];
            As[m][kb]=va.x; As[m][kb+1]=va.y; As[m][kb+2]=va.z; As[m][kb+3]=va.w;
        }
        {
            int kk = tid >> 3, nb = (tid & 7) * 8;
            const float* src = &Bb[(long long)(k0+kk)*N + n0 + nb];
            float4 v0 = *(const float4*)src;
            float4 v1 = *(const float4*)(src+4);
            Bs2[kk][nb]=v0.x; Bs2[kk][nb+1]=v0.y; Bs2[kk][nb+2]=v0.z; Bs2[kk][nb+3]=v0.w;
            Bs2[kk][nb+4]=v1.x; Bs2[kk][nb+5]=v1.y; Bs2[kk][nb+6]=v1.z; Bs2[kk][nb+7]=v1.w;
        }
        __syncthreads();
        #pragma unroll
        for(int kk=0;kk<32;kk++){
            float a0 = As[tr][kk], a1 = As[tr+16][kk];
            float4 bv = *(const float4*)&Bs2[kk][tc*4];
            acc0[0] += a0*bv.x; acc0[1] += a0*bv.y; acc0[2] += a0*bv.z; acc0[3] += a0*bv.w;
            acc1[0] += a1*bv.x; acc1[1] += a1*bv.y; acc1[2] += a1*bv.z; acc1[3] += a1*bv.w;
        }
        __syncthreads();
    }
    int colg = n0 + tc*4;
    #pragma unroll
    for(int i=0;i<2;i++){
        int m = blockIdx.y*32 + tr + i*16;
        float* accp = i ? acc1 : acc0;
        #pragma unroll
        for(int j=0;j<4;j++){
            long long idx = bz*sCz + (long long)m*N + colg + j;
            float v = accp[j];
            if(mode == 3){
                float z = Z[bz*sZz + (long long)m*N + colg + j];
                float s = sigmoidf(z);
                float ds = s*(1.f + z*(1.f - s));
                C[idx] = v*ds;
            } else {
                C[idx] = v;
            }
        }
    }
}

// ---------------- gates: theta/alpha/eta per token ----------------
__global__ void gates_kernel(const float* __restrict__ x,
                             const float* __restrict__ thw,
                             const float* __restrict__ alw,
                             const float* __restrict__ etw){
    int row = blockIdx.x;
    const float* xr = x + (long long)row*Dc;
    float st=0.f, sa=0.f, se=0.f;
    for(int d=threadIdx.x; d<Dc; d+=128){
        float xv = xr[d];
        st += xv*thw[d]; sa += xv*alw[d]; se += xv*etw[d];
    }
    st = blockReduce(st); sa = blockReduce(sa); se = blockReduce(se);
    if(threadIdx.x == 0){
        g_theta[row] = 0.01f * sigmoidf(st);
        g_alpha[row] = sigmoidf(sa);
        g_eta[row]   = sigmoidf(se);
    }
}

// ---------------- activation: silu (+ optional rms) in-place ----------------
__global__ void act_kernel(float* __restrict__ buf, const float* __restrict__ w, int mode){
    int row = blockIdx.x, d = threadIdx.x;
    long long idx = (long long)row*Dc + d;
    float v = buf[idx];
    float s = sigmoidf(v);
    float sv = v*s;
    if(mode == 0){ buf[idx] = sv; return; }
    float s2 = blockReduce(sv*sv);
    float n = rsqrtf(s2*(1.f/Dc) + 1e-6f);
    buf[idx] = sv*n*w[d];
}

// ---------------- per-token backward through rms head ----------------
__global__ void token_kernel(int ci){
    int t = blockIdx.x, b = blockIdx.y, d = threadIdx.x;
    int tok = ci*Cc + t;
    float kv = g_k[((long long)b*Sc + tok)*Dc + d];
    float vv = g_v[((long long)b*Sc + tok)*Dc + d];
    float ov = g_o[((long long)b*Cc + t)*Dc + d];
    float ln = g_Mln[b*Dc + d];
    float th = g_theta[b*Sc + tok];
    float s2 = blockReduce(ov*ov);
    float n = rsqrtf(s2*(1.f/Dc) + 1e-6f);
    float y = ln*n*ov;
    float r = kv + y - vv;
    float u = (2.f/Dc)*th*r;
    float gl = u*n*ov;
    float ws = blockReduce(u*ov*ln);
    float dov = n*ln*u - (n*n*n*ov*(1.f/Dc))*ws;
    g_do[((long long)b*Cc + t)*Dc + d] = dov;
    g_gln[((long long)b*Cc + t)*Dc + d] = gl;
    float nk = blockReduce(kv*kv);
    float nd = blockReduce(dov*dov);
    float ng = blockReduce(gl*gl);
    if(d == 0){
        g_nk[b*Cc+t] = nk; g_ndo[b*Cc+t] = nd; g_ngl[b*Cc+t] = ng;
    }
}

// ---------------- p/h norms ----------------
__global__ void pnorm_kernel(){
    int t = blockIdx.x, b = blockIdx.y;
    float sp=0.f, sh=0.f;
    const float* pp = g_p + ((long long)b*Cc + t)*Ic;
    const float* hh = g_h + ((long long)b*Cc + t)*Ic;
    for(int i=threadIdx.x;i<Ic;i+=256){ float p=pp[i], h=hh[i]; sp+=p*p; sh+=h*h; }
    sp = blockReduce(sp); sh = blockReduce(sh);
    if(threadIdx.x==0){ g_np[b*Cc+t]=sp; g_nh[b*Cc+t]=sh; }
}

// ---------------- clip coefs + scan recurrences ----------------
__global__ void coef_kernel(int ci){
    int b = blockIdx.x, u = threadIdx.x;
    int base = b*Cc;
    float sq = g_np[base+u]*g_nk[base+u] + g_ndo[base+u]*g_nh[base+u] + g_ngl[base+u];
    float coef = fminf(1.f/(sqrtf(sq)+1e-6f), 1.f);
    float eta = g_eta[b*Sc + ci*Cc + u];
    float beta = 1.f - g_alpha[b*Sc + ci*Cc + u];
    __shared__ float se[32], sb[32], sE[32], sc2[32];
    se[u]=eta; sb[u]=beta;
    __syncwarp();
    if(u==0){
        float E=1.f, F=1.f, c=1.f;
        for(int t=Cc-1;t>=0;t--){
            sE[t]=E; sc2[t]=c;
            float Fn = sb[t]*F;
            c = Fn + se[t]*c;
            E = se[t]*E;
            F = Fn;
        }
        g_A[b]=E; g_Bp[b]=F; g_cS[b]=se[0]*sc2[0];
    }
    __syncwarp();
    g_ce[base+u] = sE[u]*coef;
    g_ccoef[base+u] = sc2[u]*coef;
}

// ---------------- ln state update ----------------
__global__ void ln_update_kernel(){
    int b = blockIdx.x, d = threadIdx.x;
    float S = g_Sln[b*Dc+d], M = g_Mln[b*Dc+d];
    float sume=0.f, sumc=0.f;
    #pragma unroll
    for(int t=0;t<Cc;t++){
        float g = g_gln[((long long)b*Cc + t)*Dc + d];
        sume += g_ce[b*Cc+t]*g;
        sumc += g_ccoef[b*Cc+t]*g;
    }
    g_Sln[b*Dc+d] = g_A[b]*S - sume;
    g_Mln[b*Dc+d] = g_Bp[b]*M + g_cS[b]*S - sumc;
}

// ---------------- rank-32 state update: S' = A S - P_e^T K; M' = Bp M + cS S - P_c^T K ----------------
__global__ __launch_bounds__(256) void rank_update(
    float* __restrict__ Sm, float* __restrict__ Mm, long long stStride,
    const float* __restrict__ P, long long pStride,
    const float* __restrict__ Kv, long long kStride,
    int R, int Ccols)
{
    int b = blockIdx.z;
    Sm += b*stStride; Mm += b*stStride;
    const float* Pb = P + b*pStride;
    const float* Kb = Kv + b*kStride;
    int r0 = blockIdx.y*64, c0 = blockIdx.x*64;
    __shared__ float Ps[32][64];
    __shared__ float Ks[32][64];
    __shared__ float sce[32], scc[32];
    int tid = threadIdx.x;
    #pragma unroll
    for(int e=0;e<8;e++){
        int lin = tid + e*256;
        int t = lin >> 6, rr = lin & 63;
        Ps[t][rr] = Pb[(long long)t*R + r0 + rr];
        Ks[t][rr] = Kb[(long long)t*Ccols + c0 + rr];
    }
    if(tid < 32){ sce[tid] = g_ce[b*Cc+tid]; scc[tid] = g_ccoef[b*Cc+tid]; }
    __syncthreads();
    int tr = tid >> 4, tc = tid & 15;
    float ae[4][4] = {{0}}, ac[4][4] = {{0}};
    #pragma unroll
    for(int t=0;t<32;t++){
        float cet = sce[t], cct = scc[t];
        float4 pv = *(const float4*)&Ps[t][tr*4];
        float4 kb = *(const float4*)&Ks[t][tc*4];
        float pe[4] = {cet*pv.x, cet*pv.y, cet*pv.z, cet*pv.w};
        float pc[4] = {cct*pv.x, cct*pv.y, cct*pv.z, cct*pv.w};
        float kv4[4] = {kb.x, kb.y, kb.z, kb.w};
        #pragma unroll
        for(int i=0;i<4;i++){
            #pragma unroll
            for(int j=0;j<4;j++){
                ae[i][j] += pe[i]*kv4[j];
                ac[i][j] += pc[i]*kv4[j];
            }
        }
    }
    float A = g_A[b], Bp = g_Bp[b], cS = g_cS[b];
    #pragma unroll
    for(int i=0;i<4;i++){
        int r = r0 + tr*4 + i;
        #pragma unroll
        for(int j=0;j<4;j++){
            long long idx = (long long)r*Ccols + c0 + tc*4 + j;
            float s = Sm[idx], m = Mm[idx];
            Sm[idx] = A*s - ae[i][j];
            Mm[idx] = Bp*m + cS*s - ac[i][j];
        }
    }
}

// ---------------- final retrieval combine ----------------
__global__ void final_kernel(float* __restrict__ out){
    int row = blockIdx.x, d = threadIdx.x;
    int b = row / Sc;
    long long idx = (long long)row*Dc + d;
    float qv = g_q[idx];
    float ov = g_obuf[idx];
    float ln = g_Mln[b*Dc + d];
    float s2 = blockReduce(ov*ov);
    float n = rsqrtf(s2*(1.f/Dc) + 1e-6f);
    out[idx] = qv + ov*n*ln;
}

extern "C" void kernel_launch(void* const* d_in, const int* in_sizes, int n_in,
                              void* d_out, int out_size){
    const float* x   = (const float*)d_in[0];
    const float* wq  = (const float*)d_in[1];
    const float* wk  = (const float*)d_in[2];
    const float* wv  = (const float*)d_in[3];
    const float* qn  = (const float*)d_in[4];
    const float* kn  = (const float*)d_in[5];
    const float* alw = (const float*)d_in[6];
    const float* thw = (const float*)d_in[7];
    const float* etw = (const float*)d_in[8];
    const float* w1  = (const float*)d_in[9];
    const float* w2  = (const float*)d_in[10];
    const float* lnw = (const float*)d_in[11];
    float* out = (float*)d_out;

    float *k_, *v_, *q_, *h_, *z_, *o_, *do_, *p_, *mw1_, *sw1_, *mw2_, *sw2_, *hbuf_, *obuf_;
    cudaGetSymbolAddress((void**)&k_, g_k);
    cudaGetSymbolAddress((void**)&v_, g_v);
    cudaGetSymbolAddress((void**)&q_, g_q);
    cudaGetSymbolAddress((void**)&h_, g_h);
    cudaGetSymbolAddress((void**)&z_, g_z);
    cudaGetSymbolAddress((void**)&o_, g_o);
    cudaGetSymbolAddress((void**)&do_, g_do);
    cudaGetSymbolAddress((void**)&p_, g_p);
    cudaGetSymbolAddress((void**)&mw1_, g_MW1);
    cudaGetSymbolAddress((void**)&sw1_, g_SW1);
    cudaGetSymbolAddress((void**)&mw2_, g_MW2);
    cudaGetSymbolAddress((void**)&sw2_, g_SW2);
    cudaGetSymbolAddress((void**)&hbuf_, g_hbuf);
    cudaGetSymbolAddress((void**)&obuf_, g_obuf);

    const long long SD = (long long)Sc*Dc;   // 262144
    const long long ID = (long long)Ic*Dc;   // 524288
    const long long CI = (long long)Cc*Ic;   // 32768
    const long long CD = (long long)Cc*Dc;   // 16384
    const long long SI = (long long)Sc*Ic;   // 524288

    init_kernel<<<ID/256, 256>>>(w1, w2, lnw);

    // projections: [B*S, D] @ W^T
    gemm_nt<<<dim3(Dc/64, (Bc*Sc)/32, 1), 256>>>(x, 0, wk, 0, k_, 0, nullptr, 0, Bc*Sc, Dc, Dc, 0);
    gemm_nt<<<dim3(Dc/64, (Bc*Sc)/32, 1), 256>>>(x, 0, wv, 0, v_, 0, nullptr, 0, Bc*Sc, Dc, Dc, 0);
    gemm_nt<<<dim3(Dc/64, (Bc*Sc)/32, 1), 256>>>(x, 0, wq, 0, q_, 0, nullptr, 0, Bc*Sc, Dc, Dc, 0);
    gates_kernel<<<Bc*Sc, 128>>>(x, thw, alw, etw);
    act_kernel<<<Bc*Sc, Dc>>>(k_, kn, 1);
    act_kernel<<<Bc*Sc, Dc>>>(v_, nullptr, 0);
    act_kernel<<<Bc*Sc, Dc>>>(q_, qn, 1);

    for(int ci=0; ci<NCc; ci++){
        const float* kc = k_ + (long long)ci*Cc*Dc;   // per-batch stride SD
        // z/h = silu(Kc @ W1^T)
        gemm_nt<<<dim3(Ic/64, 1, Bc), 256>>>(kc, SD, mw1_, ID, h_, CI, z_, CI, Cc, Ic, Dc, 2);
        // o = H @ W2^T
        gemm_nt<<<dim3(Dc/64, 1, Bc), 256>>>(h_, CI, mw2_, ID, o_, CD, nullptr, 0, Cc, Dc, Ic, 0);
        token_kernel<<<dim3(Cc, Bc), Dc>>>(ci);
        // p = (DO @ W2) * silu'(z)
        gemm_nn<<<dim3(Ic/64, 1, Bc), 256>>>(do_, CD, mw2_, 0, p_, CI, z_, CI, Cc, Ic, Dc, 3);
        pnorm_kernel<<<dim3(Cc, Bc), 256>>>();
        coef_kernel<<<Bc, 32>>>(ci);
        ln_update_kernel<<<Bc, Dc>>>();
        rank_update<<<dim3(Dc/64, Ic/64, Bc), 256>>>(sw1_, mw1_, ID, p_, CI, kc, SD, Ic, Dc);
        rank_update<<<dim3(Ic/64, Dc/64, Bc), 256>>>(sw2_, mw2_, ID, do_, CD, h_, CI, Dc, Ic);
    }

    // retrieval
    gemm_nt<<<dim3(Ic/64, Sc/32, Bc), 256>>>(q_, SD, mw1_, ID, hbuf_, SI, nullptr, 0, Sc, Ic, Dc, 1);
    gemm_nt<<<dim3(Dc/64, Sc/32, Bc), 256>>>(hbuf_, SI, mw2_, ID, obuf_, SD, nullptr, 0, Sc, Dc, Ic, 0);
    final_kernel<<<Bc*Sc, Dc>>>(out);
}